// round 2
// baseline (speedup 1.0000x reference)
#include <cuda_runtime.h>
#include <cstdint>

// Problem constants
#define T_LEN 2048
#define F_DIM 32
#define B_TOT 512
#define NB 4          // batches per CTA (one per warp)

typedef unsigned long long U;   // carrier for packed f32x2

// ---- packed fp32x2 helpers (sm_103a FFMA2 path; ptxas won't auto-fuse) ----
__device__ __forceinline__ U ffma2(U a, U b, U c) {
    U d;
    asm("fma.rn.f32x2 %0, %1, %2, %3;" : "=l"(d) : "l"(a), "l"(b), "l"(c));
    return d;
}
__device__ __forceinline__ U pack2(float lo, float hi) {
    U d;
    asm("mov.b64 %0, {%1, %2};" : "=l"(d) : "f"(lo), "f"(hi));
    return d;
}
__device__ __forceinline__ float2 unpk(U d) {
    float2 r;
    asm("mov.b64 {%0, %1}, %2;" : "=f"(r.x), "=f"(r.y) : "l"(d));
    return r;
}

// ---- fast, accurate-enough activations (MUFU EX2+RCP, rel err ~1e-7) ----
__device__ __forceinline__ float sig_a(float x) {
    float e = __expf(-x);                 // handles +-inf limits gracefully
    return __fdividef(1.0f, 1.0f + e);
}
__device__ __forceinline__ float tanh_a(float x) {
    x = fminf(15.0f, fmaxf(-15.0f, x));   // clamp: avoid inf/inf -> NaN
    float e = __expf(-2.0f * x);
    return __fdividef(1.0f - e, 1.0f + e);
}

__global__ void __launch_bounds__(128, 1)
lstm_fused_kernel(const float* __restrict__ x,
                  const float* __restrict__ W_ih,
                  const float* __restrict__ W_hh,
                  const float* __restrict__ b_ih,
                  const float* __restrict__ b_hh,
                  const float* __restrict__ W_lin,
                  const float* __restrict__ b_lin,
                  float* __restrict__ out)
{
    __shared__ __align__(16) float x_sm[NB][F_DIM];       // x_t per local batch
    __shared__ __align__(16) float h_sm[NB][F_DIM];       // h_{t-1}
    __shared__ __align__(16) float z_sm[NB][2 * F_DIM];   // interleaved (h,x) for output GEMM
    __shared__ __align__(16) float g_sm[4][NB][F_DIM];    // activated gates i,f,g,o

    const int w  = threadIdx.x >> 5;   // warp id = gate id = local batch id
    const int f  = threadIdx.x & 31;   // lane = feature
    const int bg = blockIdx.x * NB + w;  // global batch this warp owns

    // ---- weights in registers as f32x2 pairs ----
    U wih2[16], whh2[16], wl2[32];
    {
        const U* pi = (const U*)(W_ih + (w * F_DIM + f) * F_DIM);
        const U* ph = (const U*)(W_hh + (w * F_DIM + f) * F_DIM);
#pragma unroll
        for (int j = 0; j < 16; j++) { wih2[j] = pi[j]; whh2[j] = ph[j]; }
        const U* pl = (const U*)(W_lin + f * (2 * F_DIM));
#pragma unroll
        for (int j = 0; j < 32; j++) wl2[j] = pl[j];
    }
    const float bias  = b_ih[w * F_DIM + f] + b_hh[w * F_DIM + f];
    const float obias = b_lin[f];

    const float* xp = x   + (size_t)bg * T_LEN * F_DIM + f;
    float*       op = out + (size_t)bg * T_LEN * F_DIM + f;

    float c = 0.0f;
    h_sm[w][f] = 0.0f;

    // prefetch x two steps ahead (cover DRAM latency)
    float xr0 = xp[0];
    float xr1 = xp[F_DIM];

    for (int t = 0; t < T_LEN; t++) {
        // ---- A: stage x_t for own batch; rotate prefetch ----
        float xcur = xr0;
        xr0 = xr1;
        xr1 = (t + 2 < T_LEN) ? xp[(size_t)(t + 2) * F_DIM] : 0.0f;
        x_sm[w][f] = xcur;

        __syncthreads();   // x_t staged, h_{t-1} stable

        // ---- C: gate pre-activations for all 4 local batches ----
        float act[NB];
#pragma unroll
        for (int b = 0; b < NB; b++) {
            const ulonglong2* xs = (const ulonglong2*)&x_sm[b][0];  // 8 x 16B, broadcast
            const ulonglong2* hs = (const ulonglong2*)&h_sm[b][0];
            U a0 = pack2(bias, 0.0f);
            U a1 = pack2(0.0f, 0.0f);
#pragma unroll
            for (int q = 0; q < 8; q++) {
                ulonglong2 xv = xs[q];                 // floats 4q..4q+3
                a0 = ffma2(wih2[2 * q],     xv.x, a0);
                a1 = ffma2(wih2[2 * q + 1], xv.y, a1);
                ulonglong2 hv = hs[q];
                a0 = ffma2(whh2[2 * q],     hv.x, a0);
                a1 = ffma2(whh2[2 * q + 1], hv.y, a1);
            }
            float2 u0 = unpk(a0), u1 = unpk(a1);
            float pre = (u0.x + u1.x) + (u0.y + u1.y);
            act[b] = (w == 2) ? tanh_a(pre) : sig_a(pre);  // gate 2 = candidate (tanh)
        }
#pragma unroll
        for (int b = 0; b < NB; b++) g_sm[w][b][f] = act[b];

        // ---- D: output stage for step t-1 (own batch; z_sm[w] written by this warp) ----
        if (t) {
            const ulonglong2* zp = (const ulonglong2*)&z_sm[w][0];   // 16 x 16B
            U a0 = pack2(obias, 0.0f);
            U a1 = pack2(0.0f, 0.0f);
#pragma unroll
            for (int q = 0; q < 16; q++) {
                ulonglong2 zv = zp[q];
                a0 = ffma2(wl2[2 * q],     zv.x, a0);
                a1 = ffma2(wl2[2 * q + 1], zv.y, a1);
            }
            float2 u0 = unpk(a0), u1 = unpk(a1);
            float s = (u0.x + u1.x) + (u0.y + u1.y);
            op[(size_t)(t - 1) * F_DIM] = tanh_a(s);
        }

        __syncthreads();   // gates visible; all h_{t-1} reads done

        // ---- E: c/h update for own batch; restage h and z ----
        float gi = g_sm[0][w][f];
        float gf = g_sm[1][w][f];
        float gg = g_sm[2][w][f];
        float go = g_sm[3][w][f];
        c = gf * c + gi * gg;
        float h = go * tanh_a(c);
        h_sm[w][f] = h;
        *(float2*)&z_sm[w][2 * f] = make_float2(h, xcur);   // z[2f]=h, z[2f+1]=x
    }

    // ---- epilogue: output for t = T-1 (z_sm[w] own-warp, no barrier needed) ----
    {
        const ulonglong2* zp = (const ulonglong2*)&z_sm[w][0];
        U a0 = pack2(obias, 0.0f);
        U a1 = pack2(0.0f, 0.0f);
#pragma unroll
        for (int q = 0; q < 16; q++) {
            ulonglong2 zv = zp[q];
            a0 = ffma2(wl2[2 * q],     zv.x, a0);
            a1 = ffma2(wl2[2 * q + 1], zv.y, a1);
        }
        float2 u0 = unpk(a0), u1 = unpk(a1);
        float s = (u0.x + u1.x) + (u0.y + u1.y);
        op[(size_t)(T_LEN - 1) * F_DIM] = tanh_a(s);
    }
}

extern "C" void kernel_launch(void* const* d_in, const int* in_sizes, int n_in,
                              void* d_out, int out_size)
{
    const float* x     = (const float*)d_in[0];
    const float* W_ih  = (const float*)d_in[1];
    const float* W_hh  = (const float*)d_in[2];
    const float* b_ih  = (const float*)d_in[3];
    const float* b_hh  = (const float*)d_in[4];
    const float* W_lin = (const float*)d_in[5];
    const float* b_lin = (const float*)d_in[6];
    float* out = (float*)d_out;

    dim3 grid(B_TOT / NB);   // 128 CTAs
    dim3 block(128);         // 4 warps: warp = gate = local batch
    lstm_fused_kernel<<<grid, block>>>(x, W_ih, W_hh, b_ih, b_hh, W_lin, b_lin, out);
}